// round 15
// baseline (speedup 1.0000x reference)
#include <cuda_runtime.h>
#include <cuda_fp16.h>
#include <cstdint>
#include <math.h>

#define NH 8
#define NN 2048
#define BM 64
#define NTILE 32
#define PDT 68

typedef unsigned long long u64;

// ---------------- k_attn smem word-offsets (single CTA = 112,928 B) ----------------
#define F_QHI  0          /* 4 strips x 4ks x 32l x 4 = 2048 words each */
#define F_QLO  2048
#define F_THI  4096
#define F_TLO  6144
#define O_K    8192       /* 64 rows x 80 = 5120 (quad rows, stride 80) */
#define O_H    13312
#define O_V    18432
#define O_EHI  23552      /* 64 rows x 36 = 2304 */
#define O_ELO  25856
#define O_MSK  28160      /* 64 ballot words */
#define O_CNT  28224      /* 8 warp popcounts */
#define SMEM_ATTN ((28232) * 4)
#define O_LX   O_EHI      /* L exchange aliases E planes in epilogue */

// ---------------- helpers ----------------
__device__ __forceinline__ void sp2(float xe, float xo, uint32_t& hi, uint32_t& lo) {
    const __half he = __float2half_rn(xe), ho = __float2half_rn(xo);
    const float re = xe - __half2float(he), ro = xo - __half2float(ho);
    const __half2 H = __halves2half2(he, ho);
    const __half2 L = __halves2half2(__float2half_rn(re), __float2half_rn(ro));
    hi = *(const uint32_t*)&H;
    lo = *(const uint32_t*)&L;
}
__device__ __forceinline__ void mma16(float c[4], uint32_t a0, uint32_t a1, uint32_t a2, uint32_t a3,
                                      uint32_t b0, uint32_t b1) {
    asm volatile(
        "mma.sync.aligned.m16n8k16.row.col.f32.f16.f16.f32 "
        "{%0,%1,%2,%3},{%4,%5,%6,%7},{%8,%9},{%0,%1,%2,%3};"
        : "+f"(c[0]), "+f"(c[1]), "+f"(c[2]), "+f"(c[3])
        : "r"(a0), "r"(a1), "r"(a2), "r"(a3), "r"(b0), "r"(b1));
}
__device__ __forceinline__ void cp16(uint32_t dst_smem, const void* src) {
    asm volatile("cp.async.cg.shared.global [%0], [%1], 16;" :: "r"(dst_smem), "l"(src));
}
#define CP_COMMIT() asm volatile("cp.async.commit_group;" ::: "memory")
#define CP_WAIT0()  asm volatile("cp.async.wait_group 0;" ::: "memory")

// -------- device scratch --------
// fragment-interleaved packed operands: uint4 = (hi_b0, hi_b1, lo_b0, lo_b1)
__device__ float g_S[NH * 64 * 64];
__device__ float g_T[NH * NN * 64];
__device__ uint4 g_Kp[NH * NN * 16];
__device__ uint4 g_Hp[NH * NN * 16];
__device__ uint4 g_Vp[NH * NTILE * 64 * 16];
__device__ unsigned int g_cnt[NH];

// ============================================================
// Kernel A: S = softmax over flattened k*k of clusters @ clusters^T
// ============================================================
__global__ void k_clusterS(const float* __restrict__ clusters) {
    __shared__ float cl[64 * 64];
    __shared__ float ds[64 * 64];
    __shared__ float red[256];
    const int h = blockIdx.x, t = threadIdx.x;
    for (int i = t; i < 4096; i += 256) cl[i] = clusters[(size_t)h * 4096 + i];
    __syncthreads();
    float lmax = -1e30f;
    for (int i = t; i < 4096; i += 256) {
        const int kk = i >> 6, jj = i & 63;
        float s = 0.f;
#pragma unroll 16
        for (int d = 0; d < 64; d++) s += cl[kk * 64 + d] * cl[jj * 64 + d];
        ds[i] = s;
        lmax = fmaxf(lmax, s);
    }
    red[t] = lmax;
    __syncthreads();
    for (int o = 128; o > 0; o >>= 1) { if (t < o) red[t] = fmaxf(red[t], red[t + o]); __syncthreads(); }
    const float mx = red[0];
    __syncthreads();
    float lsum = 0.f;
    for (int i = t; i < 4096; i += 256) { const float e = expf(ds[i] - mx); ds[i] = e; lsum += e; }
    red[t] = lsum;
    __syncthreads();
    for (int o = 128; o > 0; o >>= 1) { if (t < o) red[t] += red[t + o]; __syncthreads(); }
    const float inv = 1.f / red[0];
    for (int i = t; i < 4096; i += 256) g_S[(size_t)h * 4096 + i] = ds[i] * inv;
    if (t == 0) g_cnt[h] = 0u;
}

// ============================================================
// Kernel P: pack K and V into fragment-interleaved quads.
// ============================================================
__global__ void __launch_bounds__(256) k_prep(const float* __restrict__ K,
                                              const float* __restrict__ V) {
    __shared__ float kt[64 * 64];
    __shared__ float vt[64 * 64];
    const int tile = blockIdx.x, h = blockIdx.y, t = threadIdx.x;
    const int c0 = tile * 64;
    const float* Ksrc = K + ((size_t)h * NN + c0) * 64;
    const float* Vsrc = V + ((size_t)h * NN + c0) * 64;
    for (int i = t; i < 4096; i += 256) { kt[i] = Ksrc[i]; vt[i] = Vsrc[i]; }
    __syncthreads();
    for (int wi = t; wi < 1024; wi += 256) {
        const int n = wi >> 4, ck = wi & 15, ks = ck >> 2, lt = ck & 3;
        const int d0 = 16 * ks + 2 * lt;
        uint32_t h0, l0, h1, l1;
        sp2(kt[n * 64 + d0], kt[n * 64 + d0 + 1], h0, l0);
        sp2(kt[n * 64 + d0 + 8], kt[n * 64 + d0 + 9], h1, l1);
        g_Kp[((size_t)(h * NN + c0 + n)) * 16 + ck] = make_uint4(h0, h1, l0, l1);
    }
    for (int wi = t; wi < 1024; wi += 256) {
        const int d = wi >> 4, ck = wi & 15, ks = ck >> 2, lt = ck & 3;
        const int j0 = 16 * ks + 2 * lt;
        uint32_t h0, l0, h1, l1;
        sp2(vt[j0 * 64 + d], vt[(j0 + 1) * 64 + d], h0, l0);
        sp2(vt[(j0 + 8) * 64 + d], vt[(j0 + 9) * 64 + d], h1, l1);
        g_Vp[((size_t)((h * NTILE + tile) * 64 + d)) * 16 + ck] = make_uint4(h0, h1, l0, l1);
    }
}

// ============================================================
// k-major 64^3 SIMT GEMM helper for k_projhat (exact fp32)
// ============================================================
__device__ __forceinline__ void gemmT(const float* __restrict__ AT, const float* __restrict__ WT,
                                      int i0, int o0, float out[16]) {
    float acc[16];
#pragma unroll
    for (int q = 0; q < 16; q++) acc[q] = 0.f;
#pragma unroll 8
    for (int k = 0; k < 64; k++) {
        const float4 a = *(const float4*)&AT[k * PDT + i0];
        const float4 w = *(const float4*)&WT[k * PDT + o0];
        const float av[4] = {a.x, a.y, a.z, a.w};
        const float wv[4] = {w.x, w.y, w.z, w.w};
#pragma unroll
        for (int ii = 0; ii < 4; ii++)
#pragma unroll
            for (int jj = 0; jj < 4; jj++) acc[ii * 4 + jj] += av[ii] * wv[jj];
    }
#pragma unroll
    for (int q = 0; q < 16; q++) out[q] = acc[q];
}

__global__ void __launch_bounds__(256) k_projhat(
    const float* __restrict__ Qin, const float* __restrict__ Kin,
    const float* __restrict__ clusters, const float* __restrict__ W1,
    const float* __restrict__ b1, const float* __restrict__ W2,
    const float* __restrict__ b2) {
    extern __shared__ float smb[];
    float* AT = smb;
    float* BT = smb + 64 * PDT;
    float* WT = smb + 2 * 64 * PDT;
    const int t = threadIdx.x;
    const int h = blockIdx.y;
    const int row0 = blockIdx.x * 64;
    const int isK = blockIdx.z;
    const int ti = t >> 4, tj = t & 15, i0 = ti * 4, o0 = tj * 4;
    const float* src = (isK ? Kin : Qin) + ((size_t)h * NN + row0) * 64;

    for (int i = t; i < 4096; i += 256) {
        AT[(i & 63) * PDT + (i >> 6)] = src[i];
        WT[(i >> 6) * PDT + (i & 63)] = W1[(i & 63) * 64 + (i >> 6)];
    }
    __syncthreads();

    float out[16];
    gemmT(AT, WT, i0, o0, out);
    __syncthreads();
#pragma unroll
    for (int jj = 0; jj < 4; jj++) {
        const float bb = b1[o0 + jj];
        *(float4*)&BT[(o0 + jj) * PDT + i0] = make_float4(
            fmaxf(out[0 * 4 + jj] + bb, 0.f), fmaxf(out[1 * 4 + jj] + bb, 0.f),
            fmaxf(out[2 * 4 + jj] + bb, 0.f), fmaxf(out[3 * 4 + jj] + bb, 0.f));
    }
    for (int i = t; i < 4096; i += 256)
        WT[(i >> 6) * PDT + (i & 63)] = W2[(i & 63) * 64 + (i >> 6)];
    __syncthreads();
    gemmT(BT, WT, i0, o0, out);
    __syncthreads();
#pragma unroll
    for (int jj = 0; jj < 4; jj++) {
        const float bb = b2[o0 + jj];
        *(float4*)&AT[(o0 + jj) * PDT + i0] = make_float4(
            out[0 * 4 + jj] + bb, out[1 * 4 + jj] + bb,
            out[2 * 4 + jj] + bb, out[3 * 4 + jj] + bb);
    }
    for (int i = t; i < 4096; i += 256)
        WT[(i >> 6) * PDT + (i & 63)] = clusters[(size_t)h * 4096 + (i & 63) * 64 + (i >> 6)];
    __syncthreads();
    gemmT(AT, WT, i0, o0, out);
#pragma unroll
    for (int q = 0; q < 16; q++) out[q] = 1.f / (1.f + expf(-out[q]));

    if (isK) {
#pragma unroll
        for (int ii = 0; ii < 4; ii++) {
            const int row = row0 + i0 + ii;
            uint32_t* wbase = (uint32_t*)&g_Hp[((size_t)(h * NN + row)) * 16];
            {
                const int p = 2 * tj, ks = p >> 3, r = p & 7, lt = r & 3, slot = r >> 2;
                uint32_t hi, lo;
                sp2(out[ii * 4 + 0], out[ii * 4 + 1], hi, lo);
                wbase[(ks * 4 + lt) * 4 + slot] = hi;
                wbase[(ks * 4 + lt) * 4 + slot + 2] = lo;
            }
            {
                const int p = 2 * tj + 1, ks = p >> 3, r = p & 7, lt = r & 3, slot = r >> 2;
                uint32_t hi, lo;
                sp2(out[ii * 4 + 2], out[ii * 4 + 3], hi, lo);
                wbase[(ks * 4 + lt) * 4 + slot] = hi;
                wbase[(ks * 4 + lt) * 4 + slot + 2] = lo;
            }
        }
    } else {
        __syncthreads();
#pragma unroll
        for (int jj = 0; jj < 4; jj++)
            *(float4*)&BT[(o0 + jj) * PDT + i0] = make_float4(
                out[0 * 4 + jj], out[1 * 4 + jj], out[2 * 4 + jj], out[3 * 4 + jj]);
        for (int i = t; i < 4096; i += 256)
            WT[(i >> 6) * PDT + (i & 63)] = g_S[(size_t)h * 4096 + i];
        __syncthreads();
        gemmT(BT, WT, i0, o0, out);
#pragma unroll
        for (int ii = 0; ii < 4; ii++)
            *(float4*)&g_T[((size_t)h * NN + row0 + i0 + ii) * 64 + o0] =
                make_float4(out[ii * 4 + 0], out[ii * 4 + 1], out[ii * 4 + 2], out[ii * 4 + 3]);
    }
}

// ============================================================
// Kernel C: fused attention, fp16 m16n8k16 hi/lo splits.
// BM=64, 8 warps = 4 row-strips x 2 col-groups (16 rows x 32 cols each).
// Single-buffered tiles (cross-CTA overlap at 2 CTAs/SM hides loads).
// E exchanged via smem planes (PV j-dim spans both col-groups).
// ============================================================
__global__ void __launch_bounds__(256, 2) k_attn(
    const float* __restrict__ Qg, const int* __restrict__ maskg,
    const float* __restrict__ ug, float* __restrict__ Xout) {
    extern __shared__ float sf[];
    uint32_t* su = (uint32_t*)sf;
    const uint32_t sb4 = (uint32_t)__cvta_generic_to_shared(sf);
    const int t = threadIdx.x, l = t & 31, w = t >> 5;
    const int lg = l >> 2, lt = l & 3;
    const int s4 = w & 3, cg = w >> 2;
    const int h = blockIdx.y, row0 = blockIdx.x * BM;

    // ---- prologue 1: A-frags. cg=0 warps pack Q, cg=1 pack T (strip s4) ----
    {
        const float* As = (cg ? g_T : Qg) + ((size_t)h * NN + row0) * 64;
        const int bHI = cg ? F_THI : F_QHI;
        const int bLO = cg ? F_TLO : F_QLO;
        for (int ks = 0; ks < 4; ks++) {
#pragma unroll
            for (int i = 0; i < 4; i++) {
                const int row = 16 * s4 + lg + 8 * (i & 1);
                const int col = 16 * ks + 2 * lt + 8 * (i >> 1);
                const int fi = ((s4 * 4 + ks) * 32 + l) * 4 + i;
                const float2 v = *(const float2*)&As[row * 64 + col];
                sp2(v.x, v.y, su[bHI + fi], su[bLO + fi]);
            }
        }
    }

    // ---- prologue 2: whole-mask ballots ----
    for (int g = 0; g < 8; g++) {
        const unsigned bal = __ballot_sync(0xffffffffu, maskg[g * 256 + t] != 0);
        if (l == 0) su[O_MSK + g * 8 + w] = bal;
    }

    float Co[4][4];
#pragma unroll
    for (int nt = 0; nt < 4; nt++)
#pragma unroll
        for (int q = 0; q < 4; q++) Co[nt][q] = 0.f;
    float Lp0 = 0.f, Lp1 = 0.f;
    unsigned cnt = 0;
    const int gr0 = row0 + 16 * s4 + lg, gr1 = gr0 + 8;
    const float* u0p = ug + ((size_t)h * NN + gr0) * NN;
    const float* u1p = ug + ((size_t)h * NN + gr1) * NN;

    for (int tile = 0; tile < NTILE; tile++) {
        const int c0 = tile * 64;
        __syncthreads();   // prev tile's mma/PV reads + prologue done

        // ---- load K/H/V quads for this tile (single buffer) ----
#pragma unroll
        for (int r = 0; r < 4; r++) {
            const int wi = t + r * 256;
            const int n = wi >> 4, ck = wi & 15;
            const uint32_t doff = (n * 80 + ck * 4) * 4;
            cp16(sb4 + O_K * 4 + doff, g_Kp + (size_t)(h * NN + c0 + n) * 16 + ck);
            cp16(sb4 + O_H * 4 + doff, g_Hp + (size_t)(h * NN + c0 + n) * 16 + ck);
            cp16(sb4 + O_V * 4 + doff, g_Vp + (size_t)((h * NTILE + tile) * 64 + n) * 16 + ck);
        }
        CP_COMMIT();

        // ---- prefetch u (overlaps cp.async wait) ----
        float2 ua[4], ub[4];
#pragma unroll
        for (int nt = 0; nt < 4; nt++) {
            const int jc = c0 + cg * 32 + nt * 8 + 2 * lt;
            ua[nt] = *(const float2*)&u0p[jc];
            ub[nt] = *(const float2*)&u1p[jc];
        }
        CP_WAIT0();
        __syncthreads();

        // ---- S = QK^T (3 products), EA = T Khat^T (4 products); cols cg*32.. ----
        float Cs[4][4], Ce[4][4];
#pragma unroll
        for (int nt = 0; nt < 4; nt++)
#pragma unroll
            for (int q = 0; q < 4; q++) { Cs[nt][q] = 0.f; Ce[nt][q] = 0.f; }

        for (int ks = 0; ks < 4; ks++) {
            const int fb = ((s4 * 4 + ks) * 32 + l) * 4;
            const uint4 qh = *(const uint4*)&su[F_QHI + fb];
            const uint4 ql = *(const uint4*)&su[F_QLO + fb];
            const uint4 th = *(const uint4*)&su[F_THI + fb];
            const uint4 tl = *(const uint4*)&su[F_TLO + fb];
            uint4 kq[4], hq[4];
#pragma unroll
            for (int n = 0; n < 4; n++) {
                const int base = (cg * 32 + n * 8 + lg) * 80 + ks * 16 + lt * 4;
                kq[n] = *(const uint4*)&su[O_K + base];
                hq[n] = *(const uint4*)&su[O_H + base];
            }
#pragma unroll
            for (int n = 0; n < 4; n++) mma16(&Cs[n][0], qh.x, qh.y, qh.z, qh.w, kq[n].x, kq[n].y);
#pragma unroll
            for (int n = 0; n < 4; n++) mma16(&Ce[n][0], th.x, th.y, th.z, th.w, hq[n].x, hq[n].y);
#pragma unroll
            for (int n = 0; n < 4; n++) mma16(&Cs[n][0], qh.x, qh.y, qh.z, qh.w, kq[n].z, kq[n].w);
#pragma unroll
            for (int n = 0; n < 4; n++) mma16(&Ce[n][0], th.x, th.y, th.z, th.w, hq[n].z, hq[n].w);
#pragma unroll
            for (int n = 0; n < 4; n++) mma16(&Cs[n][0], ql.x, ql.y, ql.z, ql.w, kq[n].x, kq[n].y);
#pragma unroll
            for (int n = 0; n < 4; n++) mma16(&Ce[n][0], tl.x, tl.y, tl.z, tl.w, hq[n].x, hq[n].y);
#pragma unroll
            for (int n = 0; n < 4; n++) mma16(&Ce[n][0], tl.x, tl.y, tl.z, tl.w, hq[n].z, hq[n].w);
        }

        // ---- graph bit + exp; write E (fp16 hi/lo) into exchange planes ----
        const unsigned mw = su[O_MSK + 2 * tile + cg];
#pragma unroll
        for (int nt = 0; nt < 4; nt++) {
            const int jl = nt * 8 + 2 * lt;
            const int mA = (int)((mw >> jl) & 1u), mB = (int)((mw >> (jl + 1)) & 1u);
            const unsigned g0 = (ua[nt].x < Ce[nt][0]) ? 1u : 0u;
            const unsigned g1 = (ua[nt].y < Ce[nt][1]) ? 1u : 0u;
            const unsigned g2 = (ub[nt].x < Ce[nt][2]) ? 1u : 0u;
            const unsigned g3 = (ub[nt].y < Ce[nt][3]) ? 1u : 0u;
            cnt += g0 + g1 + g2 + g3;
            const float e0 = (g0 && mA) ? __expf(Cs[nt][0] * 0.125f) : 0.f;
            const float e1 = (g1 && mB) ? __expf(Cs[nt][1] * 0.125f) : 0.f;
            const float e2 = (g2 && mA) ? __expf(Cs[nt][2] * 0.125f) : 0.f;
            const float e3 = (g3 && mB) ? __expf(Cs[nt][3] * 0.125f) : 0.f;
            Lp0 += e0 + e1;
            Lp1 += e2 + e3;
            uint32_t h0, l0, h1, l1;
            sp2(e0, e1, h0, l0);
            sp2(e2, e3, h1, l1);
            const int jw = cg * 16 + nt * 4 + lt;
            const int r0 = 16 * s4 + lg, r1 = r0 + 8;
            su[O_EHI + r0 * 36 + jw] = h0;
            su[O_EHI + r1 * 36 + jw] = h1;
            su[O_ELO + r0 * 36 + jw] = l0;
            su[O_ELO + r1 * 36 + jw] = l1;
        }
        __syncthreads();   // E planes complete before PV reads

        // ---- PV: O += E @ V (3 products); output cols cg*32.. ----
        for (int ks = 0; ks < 4; ks++) {
            const int ea = (16 * s4 + lg) * 36 + 8 * ks + lt;
            const uint32_t ah0 = su[O_EHI + ea],           ah1 = su[O_EHI + ea + 8 * 36];
            const uint32_t ah2 = su[O_EHI + ea + 4],       ah3 = su[O_EHI + ea + 8 * 36 + 4];
            const uint32_t al0 = su[O_ELO + ea],           al1 = su[O_ELO + ea + 8 * 36];
            const uint32_t al2 = su[O_ELO + ea + 4],       al3 = su[O_ELO + ea + 8 * 36 + 4];
            uint4 vq[4];
#pragma unroll
            for (int n = 0; n < 4; n++)
                vq[n] = *(const uint4*)&su[O_V + (cg * 32 + n * 8 + lg) * 80 + ks * 16 + lt * 4];
#pragma unroll
            for (int n = 0; n < 4; n++) mma16(&Co[n][0], ah0, ah1, ah2, ah3, vq[n].x, vq[n].y);
#pragma unroll
            for (int n = 0; n < 4; n++) mma16(&Co[n][0], ah0, ah1, ah2, ah3, vq[n].z, vq[n].w);
#pragma unroll
            for (int n = 0; n < 4; n++) mma16(&Co[n][0], al0, al1, al2, al3, vq[n].x, vq[n].y);
        }
    }

    // ---- epilogue: L reduce (quad lanes + cross-col-group), X = O / L ----
    Lp0 += __shfl_xor_sync(0xffffffffu, Lp0, 1);
    Lp0 += __shfl_xor_sync(0xffffffffu, Lp0, 2);
    Lp1 += __shfl_xor_sync(0xffffffffu, Lp1, 1);
    Lp1 += __shfl_xor_sync(0xffffffffu, Lp1, 2);
    __syncthreads();   // final PV reads done; safe to alias E planes
    if (lt == 0) {
        sf[O_LX + (s4 * 2 + cg) * 16 + lg] = Lp0;
        sf[O_LX + (s4 * 2 + cg) * 16 + lg + 8] = Lp1;
    }
    __syncthreads();
    const float L0 = sf[O_LX + (s4 * 2 + 0) * 16 + lg] + sf[O_LX + (s4 * 2 + 1) * 16 + lg];
    const float L1 = sf[O_LX + (s4 * 2 + 0) * 16 + lg + 8] + sf[O_LX + (s4 * 2 + 1) * 16 + lg + 8];
    const float r0 = (L0 > 0.f) ? (1.f / L0) : 0.f;
    const float r1 = (L1 > 0.f) ? (1.f / L1) : 0.f;
    float* X0 = Xout + ((size_t)h * NN + gr0) * 64;
    float* X1 = Xout + ((size_t)h * NN + gr1) * 64;
#pragma unroll
    for (int nt = 0; nt < 4; nt++) {
        const int jc = cg * 32 + nt * 8 + 2 * lt;
        *(float2*)&X0[jc] = make_float2(Co[nt][0] * r0, Co[nt][1] * r0);
        *(float2*)&X1[jc] = make_float2(Co[nt][2] * r1, Co[nt][3] * r1);
    }

    // ---- sparsity popcount ----
#pragma unroll
    for (int off = 16; off > 0; off >>= 1) cnt += __shfl_xor_sync(0xffffffffu, cnt, off);
    if (l == 0) su[O_CNT + w] = cnt;
    __syncthreads();
    if (t == 0) {
        unsigned tot = 0;
#pragma unroll
        for (int i = 0; i < 8; i++) tot += su[O_CNT + i];
        atomicAdd(&g_cnt[h], tot);
    }
}

// ============================================================
__global__ void k_spars(float* __restrict__ out) {
    const int h = threadIdx.x;
    if (h < NH) out[h] = (float)g_cnt[h] * (1.0f / ((float)NN * (float)NN));
}

// ============================================================
extern "C" void kernel_launch(void* const* d_in, const int* in_sizes, int n_in,
                              void* d_out, int out_size) {
    (void)in_sizes; (void)n_in;
    const float* Q        = (const float*)d_in[0];
    const float* K        = (const float*)d_in[1];
    const float* V        = (const float*)d_in[2];
    const int*   mask     = (const int*)d_in[3];
    const float* u        = (const float*)d_in[4];
    const float* clusters = (const float*)d_in[5];
    const float* W1       = (const float*)d_in[6];
    const float* b1       = (const float*)d_in[7];
    const float* W2       = (const float*)d_in[8];
    const float* b2       = (const float*)d_in[9];
    float* X = (float*)d_out;
    float* spars = X + (out_size - NH);

    const int SMB = 3 * 64 * PDT * 4;
    cudaFuncSetAttribute(k_projhat, cudaFuncAttributeMaxDynamicSharedMemorySize, SMB);
    cudaFuncSetAttribute(k_attn, cudaFuncAttributeMaxDynamicSharedMemorySize, SMEM_ATTN);

    k_clusterS<<<NH, 256>>>(clusters);
    k_prep<<<dim3(NTILE, NH), 256>>>(K, V);
    k_projhat<<<dim3(NN / 64, NH, 2), 256, SMB>>>(Q, K, clusters, W1, b1, W2, b2);
    k_attn<<<dim3(NN / BM, NH), 256, SMEM_ATTN>>>(Q, mask, u, X);
    k_spars<<<1, NH>>>(spars);
}